// round 7
// baseline (speedup 1.0000x reference)
#include <cuda_runtime.h>
#include <math.h>

constexpr int NB  = 256;
constexpr int NT  = 800;
constexpr int NH  = 512;
constexpr int ND  = 128;
constexpr int NBLK = 136;      // 128 GEMM + 8 logits blocks
constexpr int NS   = 4;        // pipeline stages
constexpr int CHB_W = 16384;   // 32k x 128 cols x 4B
constexpr int CHB_H = 8192;    // 32k x 32b-dup x 8B
constexpr int STAGE = CHB_W + CHB_H;
constexpr int SMEM_DYN = NS * STAGE + 64;   // 98368

typedef unsigned long long ull;

// ---- persistent device scratch ----
__device__ __align__(16) float g_w0p[16 * 16 * 32 * 128];   // [strip][ch][k][col] 4MB
__device__ __align__(16) float g_w1p[16 * 32 * 32 * 128];   // 8MB
__device__ __align__(16) float g_wlt[16 * 32 * 128];        // [ch][k][v] 256KB
__device__ __align__(16) float g_h0d[2][8 * 16 * 32 * 64];  // [buf][btile][ch][k][bdup]
__device__ __align__(16) float g_h1d[2][8 * 16 * 32 * 64];
__device__ float g_c0[NH * NB], g_c1[NH * NB];              // [u][b]
__device__ float g_bs0[2048], g_bs1[2048];
__device__ volatile unsigned g_bar;

__device__ __forceinline__ float sigf(float x) { return 1.0f / (1.0f + __expf(-x)); }
__device__ __forceinline__ float tanhf_fast(float x) {
    x = fminf(fmaxf(x, -15.0f), 15.0f);
    float e = __expf(2.0f * x);
    return (e - 1.0f) / (e + 1.0f);
}
__device__ __forceinline__ float warp_max(float v) {
    #pragma unroll
    for (int o = 16; o; o >>= 1) v = fmaxf(v, __shfl_xor_sync(0xffffffffu, v, o));
    return v;
}
__device__ __forceinline__ float warp_sum(float v) {
    #pragma unroll
    for (int o = 16; o; o >>= 1) v += __shfl_xor_sync(0xffffffffu, v, o);
    return v;
}
#define FMA2(a, w, h) asm("fma.rn.f32x2 %0, %1, %2, %0;" : "+l"(a) : "l"(w), "l"(h))

// ---- init: pack weights into per-(strip,chunk) contiguous slabs ----
__global__ void kinit(const float* __restrict__ Whh0,
                      const float* __restrict__ bih0, const float* __restrict__ bhh0,
                      const float* __restrict__ Wih1, const float* __restrict__ Whh1,
                      const float* __restrict__ bih1, const float* __restrict__ bhh1,
                      const float* __restrict__ Wlin) {
    int i0 = blockIdx.x * blockDim.x + threadIdx.x;
    int stride = gridDim.x * blockDim.x;
    if (i0 == 0) g_bar = 0;
    // w0p: col c -> unit uu=c>>2, gate g=c&3 ; row = g*512 + s*32 + uu
    for (int off = i0; off < 16 * 65536; off += stride) {
        int s = off >> 16, r = off & 65535;
        int ch = r >> 12, kk = (r >> 7) & 31, c = r & 127;
        int row = (c & 3) * 512 + s * 32 + (c >> 2);
        g_w0p[off] = Whh0[row * 512 + ch * 32 + kk];
    }
    for (int off = i0; off < 16 * 131072; off += stride) {
        int s = off >> 17, r = off & 131071;
        int ch = r >> 12, kk = (r >> 7) & 31, c = r & 127;
        int row = (c & 3) * 512 + s * 32 + (c >> 2);
        int k = ch * 32 + kk;
        g_w1p[off] = (k < 512) ? Wih1[row * 512 + k] : Whh1[row * 512 + k - 512];
    }
    for (int off = i0; off < 65536; off += stride) {
        int ch = off >> 12, kk = (off >> 7) & 31, v = off & 127;
        g_wlt[off] = Wlin[v * 512 + ch * 32 + kk];
    }
    for (int o = i0; o < 2048; o += stride) {
        g_bs0[o] = bih0[o] + bhh0[o];
        g_bs1[o] = bih1[o] + bhh1[o];
    }
    for (int o = i0; o < NH * NB; o += stride) { g_c0[o] = 0.f; g_c1[o] = 0.f; }
    for (int o = i0; o < 8 * 16 * 32 * 64; o += stride) {
        g_h0d[0][o] = 0.f; g_h0d[1][o] = 0.f;
        g_h1d[0][o] = 0.f; g_h1d[1][o] = 0.f;
    }
}

// ---- grid barrier ----
__device__ __forceinline__ void grid_barrier(unsigned target) {
    __threadfence();
    __syncthreads();
    if (threadIdx.x == 0) {
        atomicAdd((unsigned*)&g_bar, 1u);
        while (g_bar < target) { __nanosleep(32); }
    }
    __syncthreads();
    __threadfence();
}

// ---- bulk-copy chunk issue (single thread) ----
__device__ __forceinline__ void issue_chunk(char* sm, unsigned mbar, int i,
                                            const float* wsrc, const float* hsrc) {
    if (threadIdx.x == 0) {
        int slot = i & (NS - 1);
        unsigned mb = mbar + slot * 8;
        unsigned wd = (unsigned)__cvta_generic_to_shared(sm + slot * STAGE);
        unsigned hd = wd + CHB_W;
        asm volatile("mbarrier.arrive.expect_tx.shared.b64 _, [%0], %1;"
                     :: "r"(mb), "r"((unsigned)STAGE) : "memory");
        asm volatile("cp.async.bulk.shared::cluster.global.mbarrier::complete_tx::bytes [%0], [%1], %2, [%3];"
                     :: "r"(wd), "l"(wsrc), "r"((unsigned)CHB_W), "r"(mb) : "memory");
        asm volatile("cp.async.bulk.shared::cluster.global.mbarrier::complete_tx::bytes [%0], [%1], %2, [%3];"
                     :: "r"(hd), "l"(hsrc), "r"((unsigned)CHB_H), "r"(mb) : "memory");
    }
}

__device__ __forceinline__ void wait_chunk(unsigned mbar, int i) {
    unsigned mb = mbar + (i & (NS - 1)) * 8;
    unsigned par = (unsigned)(i >> 2) & 1u;
    unsigned done;
    asm volatile(
        "{\n\t.reg .pred p;\n\t"
        "mbarrier.try_wait.parity.acquire.cta.shared::cta.b64 p, [%1], %2;\n\t"
        "selp.b32 %0, 1, 0, p;\n\t}"
        : "=r"(done) : "r"(mb), "r"(par) : "memory");
    if (!done) {
        asm volatile(
            "{\n\t.reg .pred P1;\n\t"
            "WL_%=:\n\t"
            "mbarrier.try_wait.parity.acquire.cta.shared::cta.b64 P1, [%0], %1, 0x989680;\n\t"
            "@P1 bra.uni WD_%=;\n\t"
            "bra.uni WL_%=;\n\t"
            "WD_%=:\n\t}"
            :: "r"(mb), "r"(par) : "memory");
    }
}

// ---- compute 16 k-columns of a chunk (this warp's k-half) ----
__device__ __forceinline__ void compute_chunk(ull acc[4][4], const char* sm, int slot,
                                              int co, int bo, int kh) {
    const float* wst = (const float*)(sm + slot * STAGE);
    const float* hst = (const float*)(sm + slot * STAGE + CHB_W);
    #pragma unroll
    for (int k2 = 0; k2 < 16; k2++) {
        int kk = kh * 16 + k2;
        ulonglong2 wA = *(const ulonglong2*)(wst + kk * 128 + co);
        ulonglong2 wB = *(const ulonglong2*)(wst + kk * 128 + co + 4);
        ulonglong2 hA = *(const ulonglong2*)(hst + kk * 64 + bo * 2);
        ulonglong2 hB = *(const ulonglong2*)(hst + kk * 64 + bo * 2 + 4);
        FMA2(acc[0][0], wA.x, hA.x); FMA2(acc[1][0], wA.y, hA.x);
        FMA2(acc[2][0], wB.x, hA.x); FMA2(acc[3][0], wB.y, hA.x);
        FMA2(acc[0][1], wA.x, hA.y); FMA2(acc[1][1], wA.y, hA.y);
        FMA2(acc[2][1], wB.x, hA.y); FMA2(acc[3][1], wB.y, hA.y);
        FMA2(acc[0][2], wA.x, hB.x); FMA2(acc[1][2], wA.y, hB.x);
        FMA2(acc[2][2], wB.x, hB.x); FMA2(acc[3][2], wB.y, hB.x);
        FMA2(acc[0][3], wA.x, hB.y); FMA2(acc[1][3], wA.y, hB.y);
        FMA2(acc[2][3], wB.x, hB.y); FMA2(acc[3][3], wB.y, hB.y);
    }
}

// ---- one GEMM segment (nch chunks), 4-deep bulk-copy pipeline ----
__device__ __forceinline__ void run_seg(ull acc[4][4], char* sm, unsigned mbar, int& ic,
                                        const float* wb, const float* hb0, const float* hb1,
                                        int nch, int hsw, int co, int bo, int kh) {
    #pragma unroll
    for (int j = 0; j < NS; j++) {
        const float* hs = (j < hsw) ? hb0 + j * 2048 : hb1 + (j - hsw) * 2048;
        issue_chunk(sm, mbar, ic + j, wb + j * 4096, hs);
    }
    for (int ch = 0; ch < nch; ch++) {
        int i = ic + ch;
        wait_chunk(mbar, i);
        compute_chunk(acc, sm, i & (NS - 1), co, bo, kh);
        __syncthreads();
        int nx = ch + NS;
        if (nx < nch) {
            const float* hs = (nx < hsw) ? hb0 + nx * 2048 : hb1 + (nx - hsw) * 2048;
            issue_chunk(sm, mbar, ic + nx, wb + nx * 4096, hs);
        }
    }
    ic += nch;
}

// ---- epilogue: accs -> gbuf[kh][col][b] (pitch 33) ----
__device__ __forceinline__ void store_gbuf(float* gbuf, ull acc[4][4],
                                           int co, int bo, int kh) {
    #pragma unroll
    for (int p = 0; p < 4; p++) {
        #pragma unroll
        for (int b = 0; b < 4; b++) {
            float2 v = *(float2*)&acc[p][b];
            gbuf[(kh * 128 + co + 2 * p) * 33 + bo + b]     = v.x;
            gbuf[(kh * 128 + co + 2 * p + 1) * 33 + bo + b] = v.y;
        }
    }
}

__global__ void __launch_bounds__(256, 1) lstm_persistent(
    const float* __restrict__ Wih0,     // [2048][128] = input LUT, natural layout
    const float* __restrict__ blin,
    const int* __restrict__ z, const int* __restrict__ nframes,
    float* __restrict__ out)
{
    extern __shared__ __align__(16) char sm[];
    float* gbuf = (float*)sm;   // 2*128*33 floats, aliased onto stage mem
    unsigned mbar = (unsigned)__cvta_generic_to_shared(sm + NS * STAGE);

    const int tid  = threadIdx.x;
    const int lane = tid & 31, wid = tid >> 5;
    const int kh = wid >> 2, wq = wid & 3;
    const int co = wq * 32 + (lane & 3) * 8;
    const int bo = (lane >> 2) * 4;
    const int blk = blockIdx.x;

    if (tid == 0) {
        #pragma unroll
        for (int s = 0; s < NS; s++)
            asm volatile("mbarrier.init.shared.b64 [%0], 1;" :: "r"(mbar + s * 8) : "memory");
    }
    __syncthreads();

    unsigned bar_t = 0;
    int ic = 0;

    if (blk < 128) {
        const int st = blk >> 3, bt = blk & 7, b0 = bt * 32;
        const int bl = tid & 31, uu4 = (tid >> 5) * 4;
        const int gb_ = b0 + bl;
        const float* w0 = g_w0p + st * 65536;
        const float* w1 = g_w1p + st * 131072;

        for (int t = 0; t <= NT; t++) {
            const int rd = t & 1, wr = rd ^ 1;

            // ===== phase A: layer 0 =====
            if (t < NT) {
                ull acc[4][4] = {};
                run_seg(acc, sm, mbar, ic, w0, g_h0d[rd] + bt * 32768, nullptr,
                        16, 16, co, bo, kh);
                store_gbuf(gbuf, acc, co, bo, kh);
                __syncthreads();

                int zp = (t > 0) ? z[gb_ * NT + t - 1] : 0;
                #pragma unroll
                for (int q = 0; q < 4; q++) {
                    int uu = uu4 + q, urow = st * 32 + uu, col = uu * 4;
                    float gi = gbuf[(col + 0) * 33 + bl] + gbuf[(128 + col + 0) * 33 + bl] + g_bs0[urow];
                    float gf = gbuf[(col + 1) * 33 + bl] + gbuf[(128 + col + 1) * 33 + bl] + g_bs0[512 + urow];
                    float gg = gbuf[(col + 2) * 33 + bl] + gbuf[(128 + col + 2) * 33 + bl] + g_bs0[1024 + urow];
                    float go = gbuf[(col + 3) * 33 + bl] + gbuf[(128 + col + 3) * 33 + bl] + g_bs0[1536 + urow];
                    if (t > 0) {
                        gi += Wih0[urow * 128 + zp];
                        gf += Wih0[(512 + urow) * 128 + zp];
                        gg += Wih0[(1024 + urow) * 128 + zp];
                        go += Wih0[(1536 + urow) * 128 + zp];
                    }
                    int cidx = urow * NB + gb_;
                    float c  = g_c0[cidx];
                    float cn = sigf(gf) * c + sigf(gi) * tanhf_fast(gg);
                    g_c0[cidx] = cn;
                    float hn = sigf(go) * tanhf_fast(cn);
                    int hoff = ((bt * 16 + (urow >> 5)) * 32 + (urow & 31)) * 64 + bl * 2;
                    *(float2*)&g_h0d[wr][hoff] = make_float2(hn, hn);
                }
            }
            bar_t += NBLK; grid_barrier(bar_t);

            // ===== phase B: layer 1 (32 chunks: h0 then h1) =====
            if (t < NT) {
                ull acc[4][4] = {};
                run_seg(acc, sm, mbar, ic, w1,
                        g_h0d[wr] + bt * 32768, g_h1d[rd] + bt * 32768,
                        32, 16, co, bo, kh);
                store_gbuf(gbuf, acc, co, bo, kh);
                __syncthreads();

                #pragma unroll
                for (int q = 0; q < 4; q++) {
                    int uu = uu4 + q, urow = st * 32 + uu, col = uu * 4;
                    float gi = gbuf[(col + 0) * 33 + bl] + gbuf[(128 + col + 0) * 33 + bl] + g_bs1[urow];
                    float gf = gbuf[(col + 1) * 33 + bl] + gbuf[(128 + col + 1) * 33 + bl] + g_bs1[512 + urow];
                    float gg = gbuf[(col + 2) * 33 + bl] + gbuf[(128 + col + 2) * 33 + bl] + g_bs1[1024 + urow];
                    float go = gbuf[(col + 3) * 33 + bl] + gbuf[(128 + col + 3) * 33 + bl] + g_bs1[1536 + urow];
                    int cidx = urow * NB + gb_;
                    float c  = g_c1[cidx];
                    float cn = sigf(gf) * c + sigf(gi) * tanhf_fast(gg);
                    g_c1[cidx] = cn;
                    float hn = sigf(go) * tanhf_fast(cn);
                    int hoff = ((bt * 16 + (urow >> 5)) * 32 + (urow & 31)) * 64 + bl * 2;
                    *(float2*)&g_h1d[wr][hoff] = make_float2(hn, hn);
                }
            }
            bar_t += NBLK; grid_barrier(bar_t);
        }
    } else {
        // ---------------- logits blocks: NLL for step t-1 in phase A ----------------
        const int bt = blk - 128, b0 = bt * 32;
        float nll[4];
        int nf4[4];
        #pragma unroll
        for (int bb = 0; bb < 4; bb++) {
            nll[bb] = 0.f;
            nf4[bb] = nframes[b0 + wid * 4 + bb];
        }

        for (int t = 0; t <= NT; t++) {
            const int rd = t & 1;
            if (t >= 1) {
                const int s_ = t - 1;
                ull acc[4][4] = {};
                run_seg(acc, sm, mbar, ic, g_wlt, g_h1d[rd] + bt * 32768, nullptr,
                        16, 16, co, bo, kh);
                store_gbuf(gbuf, acc, co, bo, kh);
                __syncthreads();

                #pragma unroll
                for (int bb = 0; bb < 4; bb++) {
                    int blr = wid * 4 + bb;
                    float lg[4];
                    #pragma unroll
                    for (int j = 0; j < 4; j++)
                        lg[j] = gbuf[(lane + 32 * j) * 33 + blr]
                              + gbuf[(128 + lane + 32 * j) * 33 + blr]
                              + blin[lane + 32 * j];
                    float m = fmaxf(fmaxf(lg[0], lg[1]), fmaxf(lg[2], lg[3]));
                    m = warp_max(m);
                    float se = 0.f;
                    #pragma unroll
                    for (int j = 0; j < 4; j++) se += __expf(lg[j] - m);
                    se = warp_sum(se);
                    float lse = m + logf(se);
                    int tgt = z[(b0 + blr) * NT + s_];
                    float tl = 0.f;
                    #pragma unroll
                    for (int j = 0; j < 4; j++)
                        if (lane + 32 * j == tgt) tl = lg[j];
                    tl = warp_sum(tl);
                    if (s_ < nf4[bb]) nll[bb] += (lse - tl);
                }
            }
            bar_t += NBLK; grid_barrier(bar_t);
            bar_t += NBLK; grid_barrier(bar_t);
        }

        if (lane == 0) {
            #pragma unroll
            for (int bb = 0; bb < 4; bb++)
                out[b0 + wid * 4 + bb] = nll[bb] * (1.0f / (float)NT);
        }
    }
}

extern "C" void kernel_launch(void* const* d_in, const int* in_sizes, int n_in,
                              void* d_out, int out_size) {
    const float* Wih0 = (const float*)d_in[0];
    const float* Whh0 = (const float*)d_in[1];
    const float* bih0 = (const float*)d_in[2];
    const float* bhh0 = (const float*)d_in[3];
    const float* Wih1 = (const float*)d_in[4];
    const float* Whh1 = (const float*)d_in[5];
    const float* bih1 = (const float*)d_in[6];
    const float* bhh1 = (const float*)d_in[7];
    const float* Wlin = (const float*)d_in[8];
    const float* blin = (const float*)d_in[9];
    const int*   z    = (const int*)d_in[10];
    const int*   nf   = (const int*)d_in[11];
    float* out = (float*)d_out;

    cudaFuncSetAttribute(lstm_persistent,
                         cudaFuncAttributeMaxDynamicSharedMemorySize, SMEM_DYN);
    kinit<<<256, 256>>>(Whh0, bih0, bhh0, Wih1, Whh1, bih1, bhh1, Wlin);
    lstm_persistent<<<NBLK, 256, SMEM_DYN>>>(Wih0, blin, z, nf, out);
}

// round 9
// speedup vs baseline: 2.2183x; 2.2183x over previous
#include <cuda_runtime.h>
#include <cuda_fp16.h>
#include <math.h>

typedef unsigned long long ull;
typedef unsigned int u32;
typedef unsigned short u16;

constexpr int NB = 256, NT = 800, NH = 512;
constexpr int GRID = 136;       // 128 GEMM CTAs (16 strips x 8 btiles) + 8 logits CTAs
constexpr int NS = 4;           // pipeline stages
constexpr u32 CHW = 32768;      // W frag chunk: [4 sl][2 half][8 warp][32 lane][16B]
constexpr u32 CHH = 8192;       // h frag chunk: [4 sl][2 half][4 nt][32 lane][8B]
constexpr u32 STGB = CHW + CHH; // 40KB/stage
constexpr u32 SMEM_DYN = NS * STGB + 64;   // 163904

// ---- persistent device scratch ----
__device__ __align__(128) unsigned char g_w0f[16][8][CHW];    // layer0 W frags (4MB)
__device__ __align__(128) unsigned char g_w1f[16][16][CHW];   // layer1 W frags (8MB)
__device__ __align__(128) unsigned char g_wlf[8][CHW];        // logits W frags (256KB)
__device__ __align__(128) unsigned char g_h0f[2][8][8][CHH];  // h0 frags [buf][btile][ch]
__device__ __align__(128) unsigned char g_h1f[2][8][8][CHH];
__device__ float g_c0[NH * NB], g_c1[NH * NB];                // [u][b]
__device__ float g_bs0[2048], g_bs1[2048];
__device__ float g_lut[128 * 2048];                           // [zp][gate row]
__device__ volatile unsigned g_bar;

__device__ __forceinline__ float sigf(float x) { return 1.0f / (1.0f + __expf(-x)); }
__device__ __forceinline__ float tanhf_fast(float x) {
    x = fminf(fmaxf(x, -15.0f), 15.0f);
    float e = __expf(2.0f * x);
    return (e - 1.0f) / (e + 1.0f);
}
__device__ __forceinline__ float warp_max(float v) {
    #pragma unroll
    for (int o = 16; o; o >>= 1) v = fmaxf(v, __shfl_xor_sync(0xffffffffu, v, o));
    return v;
}
__device__ __forceinline__ float warp_sum(float v) {
    #pragma unroll
    for (int o = 16; o; o >>= 1) v += __shfl_xor_sync(0xffffffffu, v, o);
    return v;
}

// split fp32 -> fp16 hi + fp16 lo
__device__ __forceinline__ void hsplit(float x, __half& h, __half& l) {
    h = __float2half_rn(x);
    l = __float2half_rn(x - __half2float(h));
}

// ---- init: pack weights into MMA fragment layout ----
// fragment elem e (fp16 index in 32KB chunk): hw=e&1, r=(e>>1)&3, t=(e>>3)&31,
// w=(e>>8)&7, half=(e>>11)&1, s=(e>>12)&3
// A frag (m16k16): m = w*16 + (t>>2) + (r&1)*8 ; k = (t&3)*2 + ((r>>1)&1)*8 + hw
__global__ void kinit(const float* __restrict__ Wih0, const float* __restrict__ Whh0,
                      const float* __restrict__ bih0, const float* __restrict__ bhh0,
                      const float* __restrict__ Wih1, const float* __restrict__ Whh1,
                      const float* __restrict__ bih1, const float* __restrict__ bhh1,
                      const float* __restrict__ Wlin) {
    int i0 = blockIdx.x * blockDim.x + threadIdx.x;
    int stride = gridDim.x * blockDim.x;
    if (i0 == 0) g_bar = 0;

    // layer0 W: 16 strips x 8 chunks x 16384 fp16
    for (int o = i0; o < 16 * 8 * 16384; o += stride) {
        int st = o >> 17, rr = o & 131071, ch = rr >> 14, e = rr & 16383;
        int hw = e & 1, r = (e >> 1) & 3, t = (e >> 3) & 31, w = (e >> 8) & 7;
        int half = (e >> 11) & 1, s = (e >> 12) & 3;
        int m = w * 16 + (t >> 2) + (r & 1) * 8;
        int kg = ch * 64 + s * 16 + (t & 3) * 2 + ((r >> 1) & 1) * 8 + hw;
        int grow = (m >> 5) * 512 + st * 32 + (m & 31);
        __half hi, lo; hsplit(Whh0[grow * 512 + kg], hi, lo);
        ((u16*)g_w0f[st][ch])[e] = __half_as_ushort(half ? lo : hi);
    }
    // layer1 W: 16 strips x 16 chunks (K=1024)
    for (int o = i0; o < 16 * 16 * 16384; o += stride) {
        int st = o >> 18, rr = o & 262143, ch = rr >> 14, e = rr & 16383;
        int hw = e & 1, r = (e >> 1) & 3, t = (e >> 3) & 31, w = (e >> 8) & 7;
        int half = (e >> 11) & 1, s = (e >> 12) & 3;
        int m = w * 16 + (t >> 2) + (r & 1) * 8;
        int kg = ch * 64 + s * 16 + (t & 3) * 2 + ((r >> 1) & 1) * 8 + hw;
        int grow = (m >> 5) * 512 + st * 32 + (m & 31);
        float v = (kg < 512) ? Wih1[grow * 512 + kg] : Whh1[grow * 512 + kg - 512];
        __half hi, lo; hsplit(v, hi, lo);
        ((u16*)g_w1f[st][ch])[e] = __half_as_ushort(half ? lo : hi);
    }
    // logits W: 8 chunks, rows = vocab directly
    for (int o = i0; o < 8 * 16384; o += stride) {
        int ch = o >> 14, e = o & 16383;
        int hw = e & 1, r = (e >> 1) & 3, t = (e >> 3) & 31, w = (e >> 8) & 7;
        int half = (e >> 11) & 1, s = (e >> 12) & 3;
        int m = w * 16 + (t >> 2) + (r & 1) * 8;
        int kg = ch * 64 + s * 16 + (t & 3) * 2 + ((r >> 1) & 1) * 8 + hw;
        __half hi, lo; hsplit(Wlin[m * 512 + kg], hi, lo);
        ((u16*)g_wlf[ch])[e] = __half_as_ushort(half ? lo : hi);
    }
    for (int o = i0; o < 128 * 2048; o += stride) {
        int zp = o >> 11, rrow = o & 2047;
        g_lut[o] = Wih0[rrow * 128 + zp];
    }
    for (int o = i0; o < 2048; o += stride) {
        g_bs0[o] = bih0[o] + bhh0[o];
        g_bs1[o] = bih1[o] + bhh1[o];
    }
    for (int o = i0; o < NH * NB; o += stride) { g_c0[o] = 0.f; g_c1[o] = 0.f; }
    ull* p0 = (ull*)&g_h0f[0][0][0][0];
    ull* p1 = (ull*)&g_h1f[0][0][0][0];
    for (int o = i0; o < (int)(sizeof(g_h0f) / 8); o += stride) { p0[o] = 0ull; p1[o] = 0ull; }
}

// ---- grid barrier ----
__device__ __forceinline__ void grid_barrier(unsigned target) {
    __threadfence();
    __syncthreads();
    if (threadIdx.x == 0) {
        atomicAdd((unsigned*)&g_bar, 1u);
        while (g_bar < target) { __nanosleep(32); }
    }
    __syncthreads();
    __threadfence();
}

// ---- bulk-copy pipeline (R6-proven) ----
__device__ __forceinline__ void issue_chunk(char* sm, unsigned mbar, int i,
                                            const unsigned char* wsrc,
                                            const unsigned char* hsrc) {
    if (threadIdx.x == 0) {
        int slot = i & (NS - 1);
        unsigned mb = mbar + slot * 8;
        unsigned wd = (unsigned)__cvta_generic_to_shared(sm + slot * STGB);
        asm volatile("mbarrier.arrive.expect_tx.shared.b64 _, [%0], %1;"
                     :: "r"(mb), "r"((unsigned)STGB) : "memory");
        asm volatile("cp.async.bulk.shared::cluster.global.mbarrier::complete_tx::bytes [%0], [%1], %2, [%3];"
                     :: "r"(wd), "l"(wsrc), "r"(CHW), "r"(mb) : "memory");
        asm volatile("cp.async.bulk.shared::cluster.global.mbarrier::complete_tx::bytes [%0], [%1], %2, [%3];"
                     :: "r"(wd + CHW), "l"(hsrc), "r"(CHH), "r"(mb) : "memory");
    }
}
__device__ __forceinline__ void wait_chunk(unsigned mbar, int i) {
    unsigned mb = mbar + (i & (NS - 1)) * 8;
    unsigned par = (unsigned)(i >> 2) & 1u;
    unsigned done;
    asm volatile("{\n\t.reg .pred p;\n\t"
                 "mbarrier.try_wait.parity.acquire.cta.shared::cta.b64 p, [%1], %2;\n\t"
                 "selp.b32 %0, 1, 0, p;\n\t}" : "=r"(done) : "r"(mb), "r"(par) : "memory");
    if (!done) {
        asm volatile("{\n\t.reg .pred P1;\n\tWL_%=:\n\t"
                     "mbarrier.try_wait.parity.acquire.cta.shared::cta.b64 P1, [%0], %1, 0x989680;\n\t"
                     "@P1 bra.uni WD_%=;\n\tbra.uni WL_%=;\n\tWD_%=:\n\t}"
                     :: "r"(mb), "r"(par) : "memory");
    }
}

// ---- HMMA: m16n8k16 fp16 x fp16 -> fp32 ----
__device__ __forceinline__ void mma16816(float* c, const uint4& a, const uint2& b) {
    asm volatile("mma.sync.aligned.m16n8k16.row.col.f32.f16.f16.f32 "
                 "{%0,%1,%2,%3}, {%4,%5,%6,%7}, {%8,%9}, {%0,%1,%2,%3};"
                 : "+f"(c[0]), "+f"(c[1]), "+f"(c[2]), "+f"(c[3])
                 : "r"(a.x), "r"(a.y), "r"(a.z), "r"(a.w), "r"(b.x), "r"(b.y));
}

// ---- compute one k64 chunk: 4 slices x (A hi/lo LDS.128 + 4nt x 3 MMA) ----
__device__ __forceinline__ void compute_chunk(float acc[4][4], const char* stg,
                                              int w, int t) {
    const char* Bb = stg + CHW;
    #pragma unroll
    for (int s = 0; s < 4; s++) {
        uint4 ahi = *(const uint4*)(stg + ((((s * 2 + 0) * 8 + w) * 32 + t) << 4));
        uint4 alo = *(const uint4*)(stg + ((((s * 2 + 1) * 8 + w) * 32 + t) << 4));
        #pragma unroll
        for (int nt = 0; nt < 4; nt++) {
            uint2 bhi = *(const uint2*)(Bb + ((((s * 2 + 0) * 4 + nt) * 32 + t) << 3));
            uint2 blo = *(const uint2*)(Bb + ((((s * 2 + 1) * 4 + nt) * 32 + t) << 3));
            mma16816(acc[nt], ahi, bhi);
            mma16816(acc[nt], ahi, blo);
            mma16816(acc[nt], alo, bhi);
        }
    }
}

// ---- one GEMM segment (nch chunks), 4-deep pipeline ----
__device__ __forceinline__ void run_seg(float acc[4][4], char* sm, unsigned mbar, int& ic,
                                        const unsigned char* wb,
                                        const unsigned char* hb0, const unsigned char* hb1,
                                        int nch, int hsw, int w, int t) {
    #pragma unroll
    for (int j = 0; j < NS; j++) {
        if (j < nch) {
            const unsigned char* hs = (j < hsw) ? hb0 + (size_t)j * CHH
                                                : hb1 + (size_t)(j - hsw) * CHH;
            issue_chunk(sm, mbar, ic + j, wb + (size_t)j * CHW, hs);
        }
    }
    for (int ch = 0; ch < nch; ch++) {
        int i = ic + ch;
        wait_chunk(mbar, i);
        compute_chunk(acc, sm + (i & 3) * STGB, w, t);
        __syncthreads();
        int nx = ch + NS;
        if (nx < nch) {
            const unsigned char* hs = (nx < hsw) ? hb0 + (size_t)nx * CHH
                                                 : hb1 + (size_t)(nx - hsw) * CHH;
            issue_chunk(sm, mbar, ic + nx, wb + (size_t)nx * CHW, hs);
        }
    }
    ic += nch;
}

// ---- acc frags -> gbuf[m][n], pitch 33 ----
__device__ __forceinline__ void store_gbuf(float* g, float acc[4][4], int w, int t) {
    int q = w * 16 + (t >> 2), c0 = (t & 3) * 2;
    #pragma unroll
    for (int nt = 0; nt < 4; nt++) {
        int c = nt * 8 + c0;
        g[q * 33 + c]           = acc[nt][0];
        g[q * 33 + c + 1]       = acc[nt][1];
        g[(q + 8) * 33 + c]     = acc[nt][2];
        g[(q + 8) * 33 + c + 1] = acc[nt][3];
    }
}

// ---- write 4 units of h (batch bl) into B-fragment slab ----
__device__ __forceinline__ void write_h(unsigned char* cb, int u0, int bl, const float* hv) {
    int s = (u0 & 63) >> 4;
    int kk0 = u0 & 15;                       // multiple of 4
    int r = kk0 >> 3;
    int tf0 = (bl & 7) * 4 + ((kk0 & 7) >> 1);
    int nt = bl >> 3;
    __half h[4], l[4];
    #pragma unroll
    for (int j = 0; j < 4; j++) hsplit(hv[j], h[j], l[j]);
    u32 hiA = (u32)__half_as_ushort(h[0]) | ((u32)__half_as_ushort(h[1]) << 16);
    u32 hiB = (u32)__half_as_ushort(h[2]) | ((u32)__half_as_ushort(h[3]) << 16);
    u32 loA = (u32)__half_as_ushort(l[0]) | ((u32)__half_as_ushort(l[1]) << 16);
    u32 loB = (u32)__half_as_ushort(l[2]) | ((u32)__half_as_ushort(l[3]) << 16);
    u32 ohi = (u32)((((s * 2 + 0) * 4 + nt) * 32 + tf0) * 8 + r * 4);
    u32 olo = (u32)((((s * 2 + 1) * 4 + nt) * 32 + tf0) * 8 + r * 4);
    *(u32*)(cb + ohi)     = hiA;
    *(u32*)(cb + ohi + 8) = hiB;
    *(u32*)(cb + olo)     = loA;
    *(u32*)(cb + olo + 8) = loB;
}

__global__ void __launch_bounds__(256, 1) lstm_mma(
    const float* __restrict__ blin,
    const int* __restrict__ z, const int* __restrict__ nframes,
    float* __restrict__ out)
{
    extern __shared__ __align__(16) char sm[];
    float* gbuf = (float*)sm;  // 128x33 fp32 aliased onto stage mem (post-GEMM)
    unsigned mbar = (unsigned)__cvta_generic_to_shared(sm + NS * STGB);

    const int tid = threadIdx.x, lane = tid & 31, wid = tid >> 5;
    const int blk = blockIdx.x;

    if (tid == 0) {
        #pragma unroll
        for (int s = 0; s < NS; s++)
            asm volatile("mbarrier.init.shared.b64 [%0], 1;" :: "r"(mbar + s * 8) : "memory");
    }
    __syncthreads();

    unsigned bar_t = 0;
    int ic = 0;

    if (blk < 128) {
        // ============ GEMM CTA: strip st (128 gate rows), batch tile bt (32) ============
        const int st = blk >> 3, bt = blk & 7, b0 = bt * 32;
        const int bl = tid & 31, uu4 = (tid >> 5) * 4;    // cell: 4 units x 1 batch
        const int gb = b0 + bl;
        const int hch = st >> 1;                          // h chunk owned by this strip

        for (int t = 0; t <= NT; t++) {
            const int rd = t & 1, wr = rd ^ 1;

            // ===== phase A: layer 0 (K=512, 8 chunks) =====
            if (t < NT) {
                float acc[4][4] = {};
                run_seg(acc, sm, mbar, ic, g_w0f[st][0],
                        g_h0f[rd][bt][0], g_h0f[rd][bt][0], 8, 8, wid, lane);
                store_gbuf(gbuf, acc, wid, lane);
                __syncthreads();

                const float* lut = (t > 0) ? g_lut + (size_t)z[gb * NT + t - 1] * 2048
                                           : nullptr;
                float hv[4];
                #pragma unroll
                for (int q = 0; q < 4; q++) {
                    int uu = uu4 + q, ug = st * 32 + uu;
                    float gi = gbuf[uu * 33 + bl]        + g_bs0[ug];
                    float gf = gbuf[(32 + uu) * 33 + bl] + g_bs0[512 + ug];
                    float gg = gbuf[(64 + uu) * 33 + bl] + g_bs0[1024 + ug];
                    float go = gbuf[(96 + uu) * 33 + bl] + g_bs0[1536 + ug];
                    if (lut) {
                        gi += lut[ug]; gf += lut[512 + ug];
                        gg += lut[1024 + ug]; go += lut[1536 + ug];
                    }
                    int ci = ug * NB + gb;
                    float c = g_c0[ci];
                    float cn = sigf(gf) * c + sigf(gi) * tanhf_fast(gg);
                    g_c0[ci] = cn;
                    hv[q] = sigf(go) * tanhf_fast(cn);
                }
                write_h(g_h0f[wr][bt][hch], st * 32 + uu4, bl, hv);
            }
            bar_t += GRID; grid_barrier(bar_t);

            // ===== phase B: layer 1 (K=1024: 8 chunks h0 new + 8 chunks h1 old) =====
            if (t < NT) {
                float acc[4][4] = {};
                run_seg(acc, sm, mbar, ic, g_w1f[st][0],
                        g_h0f[wr][bt][0], g_h1f[rd][bt][0], 16, 8, wid, lane);
                store_gbuf(gbuf, acc, wid, lane);
                __syncthreads();

                float hv[4];
                #pragma unroll
                for (int q = 0; q < 4; q++) {
                    int uu = uu4 + q, ug = st * 32 + uu;
                    float gi = gbuf[uu * 33 + bl]        + g_bs1[ug];
                    float gf = gbuf[(32 + uu) * 33 + bl] + g_bs1[512 + ug];
                    float gg = gbuf[(64 + uu) * 33 + bl] + g_bs1[1024 + ug];
                    float go = gbuf[(96 + uu) * 33 + bl] + g_bs1[1536 + ug];
                    int ci = ug * NB + gb;
                    float c = g_c1[ci];
                    float cn = sigf(gf) * c + sigf(gi) * tanhf_fast(gg);
                    g_c1[ci] = cn;
                    hv[q] = sigf(go) * tanhf_fast(cn);
                }
                write_h(g_h1f[wr][bt][hch], st * 32 + uu4, bl, hv);
            }
            bar_t += GRID; grid_barrier(bar_t);
        }
    } else {
        // ============ logits CTA: batch tile of 32, NLL for step t-1 ============
        const int bt = blk - 128, b0 = bt * 32;
        float nll[4];
        int nf4[4];
        #pragma unroll
        for (int j = 0; j < 4; j++) {
            nll[j] = 0.f;
            nf4[j] = nframes[b0 + wid * 4 + j];
        }

        for (int t = 0; t <= NT; t++) {
            const int rd = t & 1;
            if (t >= 1) {
                const int s = t - 1;
                float acc[4][4] = {};
                run_seg(acc, sm, mbar, ic, g_wlf[0],
                        g_h1f[rd][bt][0], g_h1f[rd][bt][0], 8, 8, wid, lane);
                store_gbuf(gbuf, acc, wid, lane);
                __syncthreads();

                float bl4[4];
                #pragma unroll
                for (int q = 0; q < 4; q++) bl4[q] = blin[lane + 32 * q];
                #pragma unroll
                for (int j = 0; j < 4; j++) {
                    int blr = wid * 4 + j;
                    float lg[4];
                    #pragma unroll
                    for (int q = 0; q < 4; q++)
                        lg[q] = gbuf[(lane + 32 * q) * 33 + blr] + bl4[q];
                    float m = fmaxf(fmaxf(lg[0], lg[1]), fmaxf(lg[2], lg[3]));
                    m = warp_max(m);
                    float se = 0.f;
                    #pragma unroll
                    for (int q = 0; q < 4; q++) se += __expf(lg[q] - m);
                    se = warp_sum(se);
                    float lse = m + logf(se);
                    int tgt = z[(b0 + blr) * NT + s];
                    float tl = 0.f;
                    #pragma unroll
                    for (int q = 0; q < 4; q++)
                        if (lane + 32 * q == tgt) tl = lg[q];
                    tl = warp_sum(tl);
                    if (s < nf4[j]) nll[j] += (lse - tl);
                }
                __syncthreads();
            }
            bar_t += GRID; grid_barrier(bar_t);
            bar_t += GRID; grid_barrier(bar_t);
        }

        if (lane == 0) {
            #pragma unroll
            for (int j = 0; j < 4; j++)
                out[b0 + wid * 4 + j] = nll[j] * (1.0f / (float)NT);
        }
    }
}

extern "C" void kernel_launch(void* const* d_in, const int* in_sizes, int n_in,
                              void* d_out, int out_size) {
    const float* Wih0 = (const float*)d_in[0];
    const float* Whh0 = (const float*)d_in[1];
    const float* bih0 = (const float*)d_in[2];
    const float* bhh0 = (const float*)d_in[3];
    const float* Wih1 = (const float*)d_in[4];
    const float* Whh1 = (const float*)d_in[5];
    const float* bih1 = (const float*)d_in[6];
    const float* bhh1 = (const float*)d_in[7];
    const float* Wlin = (const float*)d_in[8];
    const float* blin = (const float*)d_in[9];
    const int*   z    = (const int*)d_in[10];
    const int*   nf   = (const int*)d_in[11];
    float* out = (float*)d_out;

    cudaFuncSetAttribute(lstm_mma, cudaFuncAttributeMaxDynamicSharedMemorySize, SMEM_DYN);
    kinit<<<256, 256>>>(Wih0, Whh0, bih0, bhh0, Wih1, Whh1, bih1, bhh1, Wlin);
    lstm_mma<<<GRID, 256, SMEM_DYN>>>(blin, z, nf, out);
}